// round 8
// baseline (speedup 1.0000x reference)
#include <cuda_runtime.h>
#include <cstdint>
#include <cstddef>

#define BATCH     16384
#define DIM       64
#define NSTEPS    100
#define BPC       12                // samples per CTA
#define TPB       768               // BPC * DIM threads
#define NPAIRS    2016              // upper-triangle pairs of 64x64
#define NPAIR_TOT 2048              // 512 threads * 3 pairs + 256 threads * 2 pairs
#define MROWF     68                // padded M row (floats): conflict-free LDS.128
#define MSAMP     (DIM * MROWF)     // 4352 floats per per-sample M
#define NGROUP    ((BATCH + BPC - 1) / BPC)   // 1366 CTAs
#define GQ_TOT    32768             // float4 slots: 2048 pairs * 16 kq

typedef unsigned long long ull;

__device__ int g_idx[BATCH];
__device__ int g_perm[BATCH];
__device__ int g_pairs[NPAIR_TOT];
__device__ __align__(16) float4 g_GQ[GQ_TOT];   // tierA: [c][kq][512]; tierB @24576: [c][kq][256]

// ---------------- packed f32x2 helpers (sm_103a) ----------------
__device__ __forceinline__ ull pack2(float x, float y) {
    ull r; asm("mov.b64 %0, {%1, %2};" : "=l"(r) : "f"(x), "f"(y)); return r;
}
__device__ __forceinline__ void unpack2(ull v, float& x, float& y) {
    asm("mov.b64 {%0, %1}, %2;" : "=f"(x), "=f"(y) : "l"(v));
}
__device__ __forceinline__ ull ffma2(ull a, ull b, ull c) {
    ull d; asm("fma.rn.f32x2 %0, %1, %2, %3;" : "=l"(d) : "l"(a), "l"(b), "l"(c));
    return d;
}

// ---------------- kernel A: idx + descending counting sort + pair table ----------------
__global__ void prep_kernel(const float* __restrict__ t) {
    __shared__ int hist[NSTEPS];
    __shared__ int off[NSTEPS];
    const int tid = threadIdx.x;
    if (tid < NSTEPS) hist[tid] = 0;
    __syncthreads();
    for (int b = tid; b < BATCH; b += blockDim.x) {
        int ix = (int)truncf(100.0f * t[b]);       // trunc(n*t/T), T=1
        ix = min(max(ix, 0), NSTEPS - 1);
        g_idx[b] = ix;
        atomicAdd(&hist[ix], 1);
    }
    if (tid == 0) {                                // pair table (i<j), pad with (0,0)
        int p = 0;
        for (int i = 0; i < DIM; ++i)
            for (int j = i + 1; j < DIM; ++j)
                g_pairs[p++] = (i << 8) | j;
        for (; p < NPAIR_TOT; ++p) g_pairs[p] = 0;
    }
    __syncthreads();
    if (tid == 0) {                                // descending bins: long jobs first
        int run = 0;
        for (int bin = NSTEPS - 1; bin >= 0; --bin) { off[bin] = run; run += hist[bin]; }
    }
    __syncthreads();
    for (int b = tid; b < BATCH; b += blockDim.x) {
        int pos = atomicAdd(&off[g_idx[b]], 1);
        g_perm[pos] = b;
    }
}

// ---------------- kernel B: build two-tier float4 G planes ----------------
// tierA slot = (c*16+kq)*512 + t        (t in [0,512), c in [0,3))  -> pair 3t+c
// tierB slot = 24576 + (c*16+kq)*256+tb (tb in [0,256), c in [0,2)) -> pair 1536+2tb+c
__global__ void gt_kernel(const float* __restrict__ G) {
    int gid = blockIdx.x * blockDim.x + threadIdx.x;
    if (gid >= GQ_TOT) return;
    int c, kq, p;
    if (gid < 24576) {
        c = gid >> 13; int r = gid & 8191; kq = r >> 9; int tt = r & 511;
        p = 3 * tt + c;
    } else {
        int g2 = gid - 24576;
        c = g2 >> 12; int r = g2 & 4095; kq = r >> 8; int tb = r & 255;
        p = 1536 + 2 * tb + c;
    }
    float4 v = make_float4(0.f, 0.f, 0.f, 0.f);
    if (p < NPAIRS) {
        int pr = g_pairs[p];
        int i = pr >> 8, j = pr & 255;
        v = *reinterpret_cast<const float4*>(G + ((i * DIM + j) * DIM + 4 * kq));
    }
    g_GQ[gid] = v;
}

// ---------------- M-formation chunk: NKQ kq-groups (4 k's each) ----------------
template<int PC, int NKQ>
__device__ __forceinline__ void mform_chunk(const float4* __restrict__ gp, int gstride,
                                            const float* __restrict__ dwc, int kq0,
                                            ull (&acc)[3][6]) {
    #pragma unroll 2
    for (int kq = 0; kq < NKQ; ++kq) {
        float4 g[PC];
        #pragma unroll
        for (int c = 0; c < PC; ++c)
            g[c] = __ldg(gp + (c * 16 + (kq0 + kq)) * gstride);
        #pragma unroll
        for (int kk = 0; kk < 4; ++kk) {
            const ulonglong2* w =
                reinterpret_cast<const ulonglong2*>(dwc + (4 * (kq0 + kq) + kk) * BPC);
            ulonglong2 wa = w[0], wb = w[1], wc = w[2];
            #pragma unroll
            for (int c = 0; c < PC; ++c) {
                float gv = (kk == 0) ? g[c].x : (kk == 1) ? g[c].y : (kk == 2) ? g[c].z : g[c].w;
                ull gg = pack2(gv, gv);
                acc[c][0] = ffma2(gg, wa.x, acc[c][0]);
                acc[c][1] = ffma2(gg, wa.y, acc[c][1]);
                acc[c][2] = ffma2(gg, wb.x, acc[c][2]);
                acc[c][3] = ffma2(gg, wb.y, acc[c][3]);
                acc[c][4] = ffma2(gg, wc.x, acc[c][4]);
                acc[c][5] = ffma2(gg, wc.y, acc[c][5]);
            }
        }
    }
}

template<int PC>
__device__ __forceinline__ void mwrite(float* __restrict__ Mb,
                                       const int* upo, const int* loo, int nvalid,
                                       ull (&acc)[3][6]) {
    #pragma unroll
    for (int c = 0; c < PC; ++c) {
        if (c < nvalid) {
            float* up = Mb + upo[c];
            float* lo = Mb + loo[c];
            #pragma unroll
            for (int q = 0; q < 6; ++q) {
                float va, vb;
                unpack2(acc[c][q], va, vb);
                up[(2 * q + 0) * MSAMP] =  va;  lo[(2 * q + 0) * MSAMP] = -va;
                up[(2 * q + 1) * MSAMP] =  vb;  lo[(2 * q + 1) * MSAMP] = -vb;
            }
        }
    }
}

// ---------------- 64-dot: packed fma, conflict-free LDS.128 ----------------
__device__ __forceinline__ float dot64(const ulonglong2* __restrict__ M8,
                                       const ulonglong2* __restrict__ V8) {
    ull a0 = 0ull, a1 = 0ull;
    #pragma unroll
    for (int q = 0; q < 16; ++q) {
        ulonglong2 m = M8[q];
        ulonglong2 v = V8[q];          // broadcast within b-group
        a0 = ffma2(m.x, v.x, a0);
        a1 = ffma2(m.y, v.y, a1);
    }
    float x0, x1, z0, z1;
    unpack2(a0, x0, x1);
    unpack2(a1, z0, z1);
    return (x0 + x1) + (z0 + z1);
}

// ---------------- main integration kernel (software-pipelined) ----------------
__global__ void __launch_bounds__(TPB, 1)
sde_kernel(const float* __restrict__ y0,
           const float* __restrict__ dW,
           float* __restrict__ out)
{
    extern __shared__ __align__(16) float smem[];
    float* Msm  = smem;                        // [BPC][64][MROWF]
    float* vbuf = smem + BPC * MSAMP;          // ping-pong [2][TPB]
    float* dwT  = vbuf + 2 * TPB;              // double-buffered [2][64][BPC]

    const int tid   = threadIdx.x;
    const int b     = tid >> 6;
    const int i     = tid & 63;
    const bool tA   = (tid < 512);

    int gidx = blockIdx.x * BPC + b;
    if (gidx >= BATCH) gidx = BATCH - 1;       // ghost -> duplicate last sample (benign)
    const int sb    = g_perm[gidx];
    const int myidx = g_idx[sb];
    const int smax  = g_idx[g_perm[blockIdx.x * BPC]];   // sorted desc -> first is max

    const int PCn   = tA ? 3 : 2;
    const int pbase = tA ? 3 * tid : 1536 + 2 * (tid - 512);
    int upo[3], loo[3];
    #pragma unroll
    for (int c = 0; c < 3; ++c) {
        int pr = g_pairs[min(pbase + c, NPAIR_TOT - 1)];
        int ii = pr >> 8, jj = pr & 255;
        upo[c] = ii * MROWF + jj;
        loo[c] = jj * MROWF + ii;
    }
    const int nvalid = min(PCn, max(0, NPAIRS - pbase));

    const float4* gp = tA ? (g_GQ + tid) : (g_GQ + 24576 + (tid - 512));
    const int gstride = tA ? 512 : 256;

    Msm[b * MSAMP + i * MROWF + i] = 0.0f;     // diagonal exactly 0, set once

    float yr = y0[sb * DIM + i];

    ull acc[3][6];
    #pragma unroll
    for (int c = 0; c < 3; ++c)
        #pragma unroll
        for (int q = 0; q < 6; ++q) acc[c][q] = 0ull;

    // ---- prologue: stage dw(0), dw(1); full M-form(0); prefetch dw(2) ----
    float dw0 = dW[(size_t)sb * DIM + i];
    float dw1 = dW[((size_t)BATCH + sb) * DIM + i];
    dwT[i * BPC + b]       = dw0;              // buf0 = dw(0)
    dwT[TPB + i * BPC + b] = dw1;              // buf1 = dw(1)
    __syncthreads();
    if (tA) { for (int c4 = 0; c4 < 4; ++c4) mform_chunk<3,4>(gp, gstride, dwT, 4 * c4, acc); }
    else    { for (int c4 = 0; c4 < 4; ++c4) mform_chunk<2,4>(gp, gstride, dwT, 4 * c4, acc); }
    float r_dw = dW[((size_t)2 * BATCH + sb) * DIM + i];   // dw(2)

    const ulonglong2* Mr = reinterpret_cast<const ulonglong2*>(Msm + b * MSAMP + i * MROWF);
    const ulonglong2* V0 = reinterpret_cast<const ulonglong2*>(vbuf + b * DIM);
    const ulonglong2* V1 = reinterpret_cast<const ulonglong2*>(vbuf + TPB + b * DIM);

    for (int s = 0; s <= smax; ++s) {
        __syncthreads();                       // bar0: all reads of Msm/dwT/vbuf done
        if (tA) mwrite<3>(Msm, upo, loo, nvalid, acc);
        else    mwrite<2>(Msm, upo, loo, nvalid, acc);
        #pragma unroll
        for (int c = 0; c < 3; ++c)
            #pragma unroll
            for (int q = 0; q < 6; ++q) acc[c][q] = 0ull;
        dwT[(s & 1) * TPB + i * BPC + b] = r_dw;           // stage dw(s+2)
        vbuf[tid] = yr;                                    // v0 = y
        const float* dwc = dwT + ((s + 1) & 1) * TPB;      // dw(s+1), staged last iter
        if (tA) mform_chunk<3,4>(gp, gstride, dwc, 0, acc);
        else    mform_chunk<2,4>(gp, gstride, dwc, 0, acc);
        __syncthreads();                       // bar1: M(s), v0 visible

        float u1 = dot64(Mr, V0);
        if (tA) mform_chunk<3,3>(gp, gstride, dwc, 4, acc);
        else    mform_chunk<2,3>(gp, gstride, dwc, 4, acc);
        vbuf[TPB + tid] = yr + 0.5f * u1;
        __syncthreads();                       // bar2

        float u2 = dot64(Mr, V1);
        if (tA) mform_chunk<3,3>(gp, gstride, dwc, 7, acc);
        else    mform_chunk<2,3>(gp, gstride, dwc, 7, acc);
        vbuf[tid] = yr + 0.5f * u2;
        __syncthreads();                       // bar3

        float u3 = dot64(Mr, V0);
        if (tA) mform_chunk<3,3>(gp, gstride, dwc, 10, acc);
        else    mform_chunk<2,3>(gp, gstride, dwc, 10, acc);
        vbuf[TPB + tid] = yr + u3;
        __syncthreads();                       // bar4

        float u4 = dot64(Mr, V1);
        if (tA) mform_chunk<3,3>(gp, gstride, dwc, 13, acc);
        else    mform_chunk<2,3>(gp, gstride, dwc, 13, acc);
        yr += (u1 + 2.0f * u2 + 2.0f * u3 + u4) / 6.0f;

        if (s == myidx) out[sb * DIM + i] = yr;            // fused ys[idx_b] gather
        r_dw = dW[((size_t)min(s + 3, NSTEPS - 1) * BATCH + sb) * DIM + i];
    }
}

// ---------------- launch ----------------
extern "C" void kernel_launch(void* const* d_in, const int* in_sizes, int n_in,
                              void* d_out, int out_size) {
    const float* y0 = nullptr;
    const float* t  = nullptr;
    const float* G  = nullptr;
    const float* dW = nullptr;
    for (int k = 0; k < n_in; ++k) {           // robust size-based remap
        const float* p = (const float*)d_in[k];
        long sz = in_sizes[k];
        if      (sz == BATCH)                      t  = p;
        else if (sz == BATCH * DIM)                y0 = p;
        else if (sz == DIM * DIM * DIM)            G  = p;
        else if (sz == (long)NSTEPS * BATCH * DIM) dW = p;
    }
    float* out = (float*)d_out;

    const size_t smem_bytes =
        (size_t)(BPC * MSAMP + 2 * TPB + 2 * TPB) * sizeof(float);   // 221184 B
    cudaFuncSetAttribute(sde_kernel, cudaFuncAttributeMaxDynamicSharedMemorySize,
                         (int)smem_bytes);

    prep_kernel<<<1, 256>>>(t);
    gt_kernel<<<(GQ_TOT + 255) / 256, 256>>>(G);
    sde_kernel<<<NGROUP, TPB, smem_bytes>>>(y0, dW, out);
}

// round 9
// speedup vs baseline: 1.2824x; 1.2824x over previous
#include <cuda_runtime.h>
#include <cstdint>
#include <cstddef>

#define BATCH     16384
#define DIM       64
#define NSTEPS    100
#define BPC       12                // samples per CTA
#define TPB       768               // BPC * DIM threads
#define NPAIRS    2016              // upper-triangle pairs of 64x64
#define NPAIR_TOT 2048              // 512 threads * 3 pairs + 256 threads * 2 pairs
#define MROWF     68                // padded M row (floats): conflict-free LDS.128
#define MSAMP     (DIM * MROWF)     // 4352 floats per per-sample M
#define NGROUP    ((BATCH + BPC - 1) / BPC)   // 1366 CTAs
#define GQ_TOT    32768             // float4 slots: 2048 pairs * 16 kq

typedef unsigned long long ull;

__device__ int g_idx[BATCH];
__device__ int g_perm[BATCH];
__device__ int g_pairs[NPAIR_TOT];
__device__ __align__(16) float4 g_GQ[GQ_TOT];   // tierA: [c][kq][512]; tierB @24576: [c][kq][256]

// ---------------- packed f32x2 helpers (sm_103a) ----------------
__device__ __forceinline__ ull pack2(float x, float y) {
    ull r; asm("mov.b64 %0, {%1, %2};" : "=l"(r) : "f"(x), "f"(y)); return r;
}
__device__ __forceinline__ void unpack2(ull v, float& x, float& y) {
    asm("mov.b64 {%0, %1}, %2;" : "=f"(x), "=f"(y) : "l"(v));
}
__device__ __forceinline__ ull ffma2(ull a, ull b, ull c) {
    ull d; asm("fma.rn.f32x2 %0, %1, %2, %3;" : "=l"(d) : "l"(a), "l"(b), "l"(c));
    return d;
}
__device__ __forceinline__ void group_bar(int b) {      // 64-thread named barrier
    asm volatile("bar.sync %0, 64;" :: "r"(b + 1) : "memory");
}

// ---------------- kernel A: idx + descending counting sort + pair table ----------------
__global__ void prep_kernel(const float* __restrict__ t) {
    __shared__ int hist[NSTEPS];
    __shared__ int off[NSTEPS];
    const int tid = threadIdx.x;
    if (tid < NSTEPS) hist[tid] = 0;
    __syncthreads();
    for (int b = tid; b < BATCH; b += blockDim.x) {
        int ix = (int)truncf(100.0f * t[b]);       // trunc(n*t/T), T=1
        ix = min(max(ix, 0), NSTEPS - 1);
        g_idx[b] = ix;
        atomicAdd(&hist[ix], 1);
    }
    if (tid == 0) {                                // pair table (i<j), pad with (0,0)
        int p = 0;
        for (int i = 0; i < DIM; ++i)
            for (int j = i + 1; j < DIM; ++j)
                g_pairs[p++] = (i << 8) | j;
        for (; p < NPAIR_TOT; ++p) g_pairs[p] = 0;
    }
    __syncthreads();
    if (tid == 0) {                                // descending bins: long jobs first
        int run = 0;
        for (int bin = NSTEPS - 1; bin >= 0; --bin) { off[bin] = run; run += hist[bin]; }
    }
    __syncthreads();
    for (int b = tid; b < BATCH; b += blockDim.x) {
        int pos = atomicAdd(&off[g_idx[b]], 1);
        g_perm[pos] = b;
    }
}

// ---------------- kernel B: build two-tier float4 G planes ----------------
// tierA slot = (c*16+kq)*512 + t        (t in [0,512), c in [0,3))  -> pair 3t+c
// tierB slot = 24576 + (c*16+kq)*256+tb (tb in [0,256), c in [0,2)) -> pair 1536+2tb+c
__global__ void gt_kernel(const float* __restrict__ G) {
    int gid = blockIdx.x * blockDim.x + threadIdx.x;
    if (gid >= GQ_TOT) return;
    int c, kq, p;
    if (gid < 24576) {
        c = gid >> 13; int r = gid & 8191; kq = r >> 9; int tt = r & 511;
        p = 3 * tt + c;
    } else {
        int g2 = gid - 24576;
        c = g2 >> 12; int r = g2 & 4095; kq = r >> 8; int tb = r & 255;
        p = 1536 + 2 * tb + c;
    }
    float4 v = make_float4(0.f, 0.f, 0.f, 0.f);
    if (p < NPAIRS) {
        int pr = g_pairs[p];
        int i = pr >> 8, j = pr & 255;
        v = *reinterpret_cast<const float4*>(G + ((i * DIM + j) * DIM + 4 * kq));
    }
    g_GQ[gid] = v;
}

// ---------------- full M-formation: all 16 kq-groups, acc in registers ----------------
template<int PC>
__device__ __forceinline__ void mform_full(const float4* __restrict__ gp, int gstride,
                                           const float* __restrict__ dwc,
                                           ull (&acc)[3][6]) {
    #pragma unroll 4
    for (int kq = 0; kq < 16; ++kq) {
        float4 g[PC];
        #pragma unroll
        for (int c = 0; c < PC; ++c)
            g[c] = __ldg(gp + (c * 16 + kq) * gstride);
        #pragma unroll
        for (int kk = 0; kk < 4; ++kk) {
            const ulonglong2* w =
                reinterpret_cast<const ulonglong2*>(dwc + (4 * kq + kk) * BPC);
            ulonglong2 wa = w[0], wb = w[1], wc = w[2];   // 12 samples, broadcast LDS
            #pragma unroll
            for (int c = 0; c < PC; ++c) {
                float gv = (kk == 0) ? g[c].x : (kk == 1) ? g[c].y
                         : (kk == 2) ? g[c].z : g[c].w;
                ull gg = pack2(gv, gv);
                acc[c][0] = ffma2(gg, wa.x, acc[c][0]);
                acc[c][1] = ffma2(gg, wa.y, acc[c][1]);
                acc[c][2] = ffma2(gg, wb.x, acc[c][2]);
                acc[c][3] = ffma2(gg, wb.y, acc[c][3]);
                acc[c][4] = ffma2(gg, wc.x, acc[c][4]);
                acc[c][5] = ffma2(gg, wc.y, acc[c][5]);
            }
        }
    }
}

template<int PC>
__device__ __forceinline__ void mwrite(float* __restrict__ Mb,
                                       const int* upo, const int* loo, int nvalid,
                                       ull (&acc)[3][6]) {
    #pragma unroll
    for (int c = 0; c < PC; ++c) {
        if (c < nvalid) {
            float* up = Mb + upo[c];
            float* lo = Mb + loo[c];
            #pragma unroll
            for (int q = 0; q < 6; ++q) {
                float va, vb;
                unpack2(acc[c][q], va, vb);
                up[(2 * q + 0) * MSAMP] =  va;  lo[(2 * q + 0) * MSAMP] = -va;
                up[(2 * q + 1) * MSAMP] =  vb;  lo[(2 * q + 1) * MSAMP] = -vb;
            }
        }
    }
}

// ---------------- 64-dot: packed fma, conflict-free LDS.128 ----------------
__device__ __forceinline__ float dot64(const ulonglong2* __restrict__ M8,
                                       const ulonglong2* __restrict__ V8) {
    ull a0 = 0ull, a1 = 0ull;
    #pragma unroll
    for (int q = 0; q < 16; ++q) {
        ulonglong2 m = M8[q];
        ulonglong2 v = V8[q];          // broadcast within b-group
        a0 = ffma2(m.x, v.x, a0);
        a1 = ffma2(m.y, v.y, a1);
    }
    float x0, x1, z0, z1;
    unpack2(a0, x0, x1);
    unpack2(a1, z0, z1);
    return (x0 + x1) + (z0 + z1);
}

// ---------------- main integration kernel (R4 structure, BPC=12, named bars) ----------------
__global__ void __launch_bounds__(TPB)
sde_kernel(const float* __restrict__ y0,
           const float* __restrict__ dW,
           float* __restrict__ out)
{
    extern __shared__ __align__(16) float smem[];
    float* Msm  = smem;                        // [BPC][64][MROWF]
    float* vbuf = smem + BPC * MSAMP;          // ping-pong [2][TPB]
    float* dwT  = vbuf + 2 * TPB;              // [64][BPC]

    const int tid = threadIdx.x;
    const int b   = tid >> 6;
    const int i   = tid & 63;
    const bool tA = (tid < 512);

    int gidx = blockIdx.x * BPC + b;
    if (gidx >= BATCH) gidx = BATCH - 1;       // ghost -> duplicate last sample (benign)
    const int sb    = g_perm[gidx];
    const int myidx = g_idx[sb];
    const int smax  = g_idx[g_perm[blockIdx.x * BPC]];   // sorted desc -> first is max

    const int pbase = tA ? 3 * tid : 1536 + 2 * (tid - 512);
    int upo[3], loo[3];
    #pragma unroll
    for (int c = 0; c < 3; ++c) {
        int pr = g_pairs[min(pbase + c, NPAIR_TOT - 1)];
        int ii = pr >> 8, jj = pr & 255;
        upo[c] = ii * MROWF + jj;
        loo[c] = jj * MROWF + ii;
    }
    const int nvalid = min(tA ? 3 : 2, max(0, NPAIRS - pbase));

    const float4* gp  = tA ? (g_GQ + tid) : (g_GQ + 24576 + (tid - 512));
    const int gstride = tA ? 512 : 256;

    Msm[b * MSAMP + i * MROWF + i] = 0.0f;     // diagonal exactly 0, set once

    float yr   = y0[sb * DIM + i];
    float r_dw = dW[(size_t)sb * DIM + i];     // dw(0)

    const ulonglong2* Mr = reinterpret_cast<const ulonglong2*>(Msm + b * MSAMP + i * MROWF);
    const ulonglong2* V0 = reinterpret_cast<const ulonglong2*>(vbuf + b * DIM);
    const ulonglong2* V1 = reinterpret_cast<const ulonglong2*>(vbuf + TPB + b * DIM);

    for (int s = 0; s <= smax; ++s) {
        dwT[i * BPC + b] = r_dw;               // stage dw(s) transposed [k][b]
        vbuf[tid] = yr;                        // v0 = y
        __syncthreads();                       // barA: dwT/v0 ready; prior M/dwT reads done

        r_dw = dW[((size_t)min(s + 1, NSTEPS - 1) * BATCH + sb) * DIM + i];  // prefetch

        ull acc[3][6];
        #pragma unroll
        for (int c = 0; c < 3; ++c)
            #pragma unroll
            for (int q = 0; q < 6; ++q) acc[c][q] = 0ull;

        if (tA) { mform_full<3>(gp, gstride, dwT, acc); mwrite<3>(Msm, upo, loo, nvalid, acc); }
        else    { mform_full<2>(gp, gstride, dwT, acc); mwrite<2>(Msm, upo, loo, nvalid, acc); }
        __syncthreads();                       // barB: M(s) complete & visible

        // ---- RK4 stages; per-sample 64-thread named barriers (no block convoy) ----
        float u1 = dot64(Mr, V0);
        vbuf[TPB + tid] = yr + 0.5f * u1;
        group_bar(b);

        float u2 = dot64(Mr, V1);
        vbuf[tid] = yr + 0.5f * u2;
        group_bar(b);

        float u3 = dot64(Mr, V0);
        vbuf[TPB + tid] = yr + u3;
        group_bar(b);

        float u4 = dot64(Mr, V1);
        yr += (u1 + 2.0f * u2 + 2.0f * u3 + u4) / 6.0f;

        if (s == myidx) out[sb * DIM + i] = yr;            // fused ys[idx_b] gather
        // loop-top barA covers WAR on dwT/vbuf/Msm for next step
    }
}

// ---------------- launch ----------------
extern "C" void kernel_launch(void* const* d_in, const int* in_sizes, int n_in,
                              void* d_out, int out_size) {
    const float* y0 = nullptr;
    const float* t  = nullptr;
    const float* G  = nullptr;
    const float* dW = nullptr;
    for (int k = 0; k < n_in; ++k) {           // robust size-based remap
        const float* p = (const float*)d_in[k];
        long sz = in_sizes[k];
        if      (sz == BATCH)                      t  = p;
        else if (sz == BATCH * DIM)                y0 = p;
        else if (sz == DIM * DIM * DIM)            G  = p;
        else if (sz == (long)NSTEPS * BATCH * DIM) dW = p;
    }
    float* out = (float*)d_out;

    const size_t smem_bytes =
        (size_t)(BPC * MSAMP + 2 * TPB + DIM * BPC) * sizeof(float);   // 218112 B
    cudaFuncSetAttribute(sde_kernel, cudaFuncAttributeMaxDynamicSharedMemorySize,
                         (int)smem_bytes);

    prep_kernel<<<1, 256>>>(t);
    gt_kernel<<<(GQ_TOT + 255) / 256, 256>>>(G);
    sde_kernel<<<NGROUP, TPB, smem_bytes>>>(y0, dW, out);
}

// round 10
// speedup vs baseline: 1.3638x; 1.0635x over previous
#include <cuda_runtime.h>
#include <cstdint>
#include <cstddef>

#define BATCH     16384
#define DIM       64
#define NSTEPS    100
#define BPC       12                // samples per CTA (smem ceiling)
#define TPB       768               // BPC * DIM threads
#define NPAIRS    2016              // upper-triangle pairs of 64x64
#define NPAIR_TOT 2048              // 512 threads * 3 pairs + 256 threads * 2 pairs
#define MROWF     68                // padded M row (floats): conflict-free LDS.128
#define MSAMP     (DIM * MROWF)     // 4352 floats per per-sample M
#define NGROUP    ((BATCH + BPC - 1) / BPC)   // 1366 CTAs
#define GQ_TOT    32768             // float4 slots: 2048 pairs * 16 kq

typedef unsigned long long ull;

__device__ int g_idx[BATCH];
__device__ int g_perm[BATCH];
__device__ int g_pairs[NPAIR_TOT];
__device__ __align__(16) float4 g_GQ[GQ_TOT];   // tierA: [c][kq][512]; tierB @24576: [c][kq][256]

// ---------------- packed f32x2 helpers (sm_103a) ----------------
__device__ __forceinline__ ull pack2(float x, float y) {
    ull r; asm("mov.b64 %0, {%1, %2};" : "=l"(r) : "f"(x), "f"(y)); return r;
}
__device__ __forceinline__ void unpack2(ull v, float& x, float& y) {
    asm("mov.b64 {%0, %1}, %2;" : "=f"(x), "=f"(y) : "l"(v));
}
__device__ __forceinline__ ull ffma2(ull a, ull b, ull c) {
    ull d; asm("fma.rn.f32x2 %0, %1, %2, %3;" : "=l"(d) : "l"(a), "l"(b), "l"(c));
    return d;
}
__device__ __forceinline__ void group_bar(int b) {      // 64-thread named barrier
    asm volatile("bar.sync %0, 64;" :: "r"(b + 1) : "memory");
}

// ---------------- setup: idx + descending counting sort + pair table + G planes ----
// Single CTA so the launch sequence is [setup, sde] per replay (better ncu slotting).
__global__ void setup_kernel(const float* __restrict__ t, const float* __restrict__ G) {
    __shared__ int hist[NSTEPS];
    __shared__ int off[NSTEPS];
    const int tid = threadIdx.x;                   // 512 threads
    if (tid < NSTEPS) hist[tid] = 0;
    __syncthreads();
    for (int b = tid; b < BATCH; b += blockDim.x) {
        int ix = (int)truncf(100.0f * t[b]);       // trunc(n*t/T), T=1
        ix = min(max(ix, 0), NSTEPS - 1);
        g_idx[b] = ix;
        atomicAdd(&hist[ix], 1);
    }
    if (tid == 0) {                                // pair table (i<j), pad with (0,0)
        int p = 0;
        for (int i = 0; i < DIM; ++i)
            for (int j = i + 1; j < DIM; ++j)
                g_pairs[p++] = (i << 8) | j;
        for (; p < NPAIR_TOT; ++p) g_pairs[p] = 0;
    }
    __syncthreads();
    if (tid == 0) {                                // descending bins: long jobs first
        int run = 0;
        for (int bin = NSTEPS - 1; bin >= 0; --bin) { off[bin] = run; run += hist[bin]; }
    }
    __syncthreads();
    for (int b = tid; b < BATCH; b += blockDim.x) {
        int pos = atomicAdd(&off[g_idx[b]], 1);
        g_perm[pos] = b;
    }
    // ---- G planes ----
    // tierA slot = (c*16+kq)*512 + t        (t in [0,512), c in [0,3))  -> pair 3t+c
    // tierB slot = 24576 + (c*16+kq)*256+tb (tb in [0,256), c in [0,2)) -> pair 1536+2tb+c
    for (int gid = tid; gid < GQ_TOT; gid += blockDim.x) {
        int c, kq, p;
        if (gid < 24576) {
            c = gid >> 13; int r = gid & 8191; kq = r >> 9; int tt = r & 511;
            p = 3 * tt + c;
        } else {
            int g2 = gid - 24576;
            c = g2 >> 12; int r = g2 & 4095; kq = r >> 8; int tb = r & 255;
            p = 1536 + 2 * tb + c;
        }
        float4 v = make_float4(0.f, 0.f, 0.f, 0.f);
        if (p < NPAIRS) {
            int pr = g_pairs[p];
            int i = pr >> 8, j = pr & 255;
            v = *reinterpret_cast<const float4*>(G + ((i * DIM + j) * DIM + 4 * kq));
        }
        g_GQ[gid] = v;
    }
}

// ---------------- full M-formation: all 16 kq-groups, acc in registers ----------------
template<int PC>
__device__ __forceinline__ void mform_full(const float4* __restrict__ gp, int gstride,
                                           const float* __restrict__ dwc,
                                           ull (&acc)[3][6]) {
    #pragma unroll 4
    for (int kq = 0; kq < 16; ++kq) {
        float4 g[PC];
        #pragma unroll
        for (int c = 0; c < PC; ++c)
            g[c] = __ldg(gp + (c * 16 + kq) * gstride);
        #pragma unroll
        for (int kk = 0; kk < 4; ++kk) {
            const ulonglong2* w =
                reinterpret_cast<const ulonglong2*>(dwc + (4 * kq + kk) * BPC);
            ulonglong2 wa = w[0], wb = w[1], wc = w[2];   // 12 samples, broadcast LDS
            #pragma unroll
            for (int c = 0; c < PC; ++c) {
                float gv = (kk == 0) ? g[c].x : (kk == 1) ? g[c].y
                         : (kk == 2) ? g[c].z : g[c].w;
                ull gg = pack2(gv, gv);
                acc[c][0] = ffma2(gg, wa.x, acc[c][0]);
                acc[c][1] = ffma2(gg, wa.y, acc[c][1]);
                acc[c][2] = ffma2(gg, wb.x, acc[c][2]);
                acc[c][3] = ffma2(gg, wb.y, acc[c][3]);
                acc[c][4] = ffma2(gg, wc.x, acc[c][4]);
                acc[c][5] = ffma2(gg, wc.y, acc[c][5]);
            }
        }
    }
}

template<int PC>
__device__ __forceinline__ void mwrite(float* __restrict__ Mb,
                                       const int* upo, const int* loo, int nvalid,
                                       ull (&acc)[3][6]) {
    #pragma unroll
    for (int c = 0; c < PC; ++c) {
        if (c < nvalid) {
            float* up = Mb + upo[c];
            float* lo = Mb + loo[c];
            #pragma unroll
            for (int q = 0; q < 6; ++q) {
                float va, vb;
                unpack2(acc[c][q], va, vb);
                up[(2 * q + 0) * MSAMP] =  va;  lo[(2 * q + 0) * MSAMP] = -va;
                up[(2 * q + 1) * MSAMP] =  vb;  lo[(2 * q + 1) * MSAMP] = -vb;
            }
        }
    }
}

// ---------------- half-register 64-dot ----------------
// Front half (cols 0..31) from registers, back half (cols 32..63) from smem.
// Contraction order identical to the previous full-smem dot64 (q = 0..15).
__device__ __forceinline__ float dot64h(const ulonglong2 (&Mreg)[8],
                                        const ulonglong2* __restrict__ Mhi,
                                        const ulonglong2* __restrict__ V8) {
    ull a0 = 0ull, a1 = 0ull;
    #pragma unroll
    for (int q = 0; q < 8; ++q) {
        ulonglong2 v = V8[q];                    // broadcast within b-group
        a0 = ffma2(Mreg[q].x, v.x, a0);
        a1 = ffma2(Mreg[q].y, v.y, a1);
    }
    #pragma unroll
    for (int q = 0; q < 8; ++q) {
        ulonglong2 m = Mhi[q];                   // LDS.128, conflict-free
        ulonglong2 v = V8[8 + q];
        a0 = ffma2(m.x, v.x, a0);
        a1 = ffma2(m.y, v.y, a1);
    }
    float x0, x1, z0, z1;
    unpack2(a0, x0, x1);
    unpack2(a1, z0, z1);
    return (x0 + x1) + (z0 + z1);
}

// ---------------- main integration kernel ----------------
__global__ void __launch_bounds__(TPB)
sde_kernel(const float* __restrict__ y0,
           const float* __restrict__ dW,
           float* __restrict__ out)
{
    extern __shared__ __align__(16) float smem[];
    float* Msm  = smem;                        // [BPC][64][MROWF]
    float* vbuf = smem + BPC * MSAMP;          // ping-pong [2][TPB]
    float* dwT  = vbuf + 2 * TPB;              // [64][BPC]

    const int tid = threadIdx.x;
    const int b   = tid >> 6;
    const int i   = tid & 63;
    const bool tA = (tid < 512);

    int gidx = blockIdx.x * BPC + b;
    if (gidx >= BATCH) gidx = BATCH - 1;       // ghost -> duplicate last sample (benign)
    const int sb    = g_perm[gidx];
    const int myidx = g_idx[sb];
    const int smax  = g_idx[g_perm[blockIdx.x * BPC]];   // sorted desc -> first is max

    const int pbase = tA ? 3 * tid : 1536 + 2 * (tid - 512);
    int upo[3], loo[3];
    #pragma unroll
    for (int c = 0; c < 3; ++c) {
        int pr = g_pairs[min(pbase + c, NPAIR_TOT - 1)];
        int ii = pr >> 8, jj = pr & 255;
        upo[c] = ii * MROWF + jj;
        loo[c] = jj * MROWF + ii;
    }
    const int nvalid = min(tA ? 3 : 2, max(0, NPAIRS - pbase));

    const float4* gp  = tA ? (g_GQ + tid) : (g_GQ + 24576 + (tid - 512));
    const int gstride = tA ? 512 : 256;

    Msm[b * MSAMP + i * MROWF + i] = 0.0f;     // diagonal exactly 0, set once

    float yr   = y0[sb * DIM + i];
    float r_dw = dW[(size_t)sb * DIM + i];     // dw(0)

    const ulonglong2* Mr  = reinterpret_cast<const ulonglong2*>(Msm + b * MSAMP + i * MROWF);
    const ulonglong2* Mhi = Mr + 8;            // back half of the row (smem)
    const ulonglong2* V0  = reinterpret_cast<const ulonglong2*>(vbuf + b * DIM);
    const ulonglong2* V1  = reinterpret_cast<const ulonglong2*>(vbuf + TPB + b * DIM);

    for (int s = 0; s <= smax; ++s) {
        dwT[i * BPC + b] = r_dw;               // stage dw(s) transposed [k][b]
        vbuf[tid] = yr;                        // v0 = y
        __syncthreads();                       // barA: dwT/v0 ready; prior M/dwT reads done

        r_dw = dW[((size_t)min(s + 1, NSTEPS - 1) * BATCH + sb) * DIM + i];  // prefetch

        ull acc[3][6];
        #pragma unroll
        for (int c = 0; c < 3; ++c)
            #pragma unroll
            for (int q = 0; q < 6; ++q) acc[c][q] = 0ull;

        if (tA) { mform_full<3>(gp, gstride, dwT, acc); mwrite<3>(Msm, upo, loo, nvalid, acc); }
        else    { mform_full<2>(gp, gstride, dwT, acc); mwrite<2>(Msm, upo, loo, nvalid, acc); }
        __syncthreads();                       // barB: M(s) complete & visible

        // Load the front half of my M row into registers; reused by all 4 stages.
        ulonglong2 Mreg[8];
        #pragma unroll
        for (int q = 0; q < 8; ++q) Mreg[q] = Mr[q];

        // ---- RK4 stages; per-sample 64-thread named barriers (no block convoy) ----
        float u1 = dot64h(Mreg, Mhi, V0);
        vbuf[TPB + tid] = yr + 0.5f * u1;
        group_bar(b);

        float u2 = dot64h(Mreg, Mhi, V1);
        vbuf[tid] = yr + 0.5f * u2;
        group_bar(b);

        float u3 = dot64h(Mreg, Mhi, V0);
        vbuf[TPB + tid] = yr + u3;
        group_bar(b);

        float u4 = dot64h(Mreg, Mhi, V1);
        yr += (u1 + 2.0f * u2 + 2.0f * u3 + u4) / 6.0f;

        if (s == myidx) out[sb * DIM + i] = yr;            // fused ys[idx_b] gather
        // loop-top barA covers WAR on dwT/vbuf/Msm for next step
    }
}

// ---------------- launch ----------------
extern "C" void kernel_launch(void* const* d_in, const int* in_sizes, int n_in,
                              void* d_out, int out_size) {
    const float* y0 = nullptr;
    const float* t  = nullptr;
    const float* G  = nullptr;
    const float* dW = nullptr;
    for (int k = 0; k < n_in; ++k) {           // robust size-based remap
        const float* p = (const float*)d_in[k];
        long sz = in_sizes[k];
        if      (sz == BATCH)                      t  = p;
        else if (sz == BATCH * DIM)                y0 = p;
        else if (sz == DIM * DIM * DIM)            G  = p;
        else if (sz == (long)NSTEPS * BATCH * DIM) dW = p;
    }
    float* out = (float*)d_out;

    const size_t smem_bytes =
        (size_t)(BPC * MSAMP + 2 * TPB + DIM * BPC) * sizeof(float);   // 218112 B
    cudaFuncSetAttribute(sde_kernel, cudaFuncAttributeMaxDynamicSharedMemorySize,
                         (int)smem_bytes);

    setup_kernel<<<1, 512>>>(t, G);
    sde_kernel<<<NGROUP, TPB, smem_bytes>>>(y0, dW, out);
}